// round 10
// baseline (speedup 1.0000x reference)
#include <cuda_runtime.h>

#define Nn    50000
#define Ee    800000
#define Ff    4
#define Tt    12
#define Cc    32
#define HORZ  12
#define FT    (Ff*Tt)     // 48
#define TILE  512
#define NTILES ((Nn + TILE - 1) / TILE)   // 98

// ---------------- scratch (device globals; no allocation allowed) ----------
// zeroed each run by one cudaMemsetAsync:
//   [0, Nn)   : weighted degree (float)
//   [Nn, 2Nn) : edge count (int)
//   [2Nn]     : done-counter for last-block scan
__device__ unsigned int g_zero[2*Nn + 1];
__device__ float  g_dis[Nn];
__device__ int    g_ptrloc[Nn];       // tile-local exclusive scan of counts
__device__ int    g_cur[Nn];          // scatter cursors (tile-local)
__device__ int    g_tilesum[NTILES];
__device__ int    g_tileoff[NTILES];  // exclusive scan of tile sums
__device__ int2   g_edge[Ee];         // packed CSR payload {row, norm bits}
__device__ float  g_Mz[Ff*Cc];        // Wz @ Wlz[:C]
__device__ float  g_Mh[Ff*Cc];        // Wh @ Wlh[:C]
__device__ float  g_cz[Cc];           // bz @ Wlz[:C] + blz
__device__ float  g_ch[Cc];
__device__ float  g_probs[Tt];

static __device__ __forceinline__ float tanh_fast(float v) {
    float r;
    asm("tanh.approx.f32 %0, %1;" : "=f"(r) : "f"(v));
    return r;
}

// ---------------- histogram + (block 0) folded-weight setup ---------------
__global__ void k_hist(const int* __restrict__ ei, const float* __restrict__ ew,
                       const float* __restrict__ att,
                       const float* __restrict__ Wz, const float* __restrict__ bz,
                       const float* __restrict__ Wlz, const float* __restrict__ blz,
                       const float* __restrict__ Wh, const float* __restrict__ bh,
                       const float* __restrict__ Wlh, const float* __restrict__ blh) {
    float* deg = (float*)g_zero;
    int*   cnt = (int*)(g_zero + Nn);
    int e = blockIdx.x * blockDim.x + threadIdx.x;
    if (e < Ee) {
        int col = ei[Ee + e];
        atomicAdd(&deg[col], ew[e]);
        atomicAdd(&cnt[col], 1);
    }
    // block 0 additionally folds the weights (H0 == 0 forever -> R gate dead,
    // concat collapses: M = W @ Wl[:C], c = b @ Wl[:C] + bl)
    if (blockIdx.x == 0) {
        int tid = threadIdx.x;
        if (tid < Ff*Cc) {
            int f = tid / Cc, c = tid % Cc;
            float sz = 0.f, sh = 0.f;
            #pragma unroll
            for (int k = 0; k < Cc; ++k) {
                sz += Wz[f*Cc + k] * Wlz[k*Cc + c];
                sh += Wh[f*Cc + k] * Wlh[k*Cc + c];
            }
            g_Mz[tid] = sz;
            g_Mh[tid] = sh;
        }
        if (tid < Cc) {
            float sz = 0.f, sh = 0.f;
            #pragma unroll
            for (int k = 0; k < Cc; ++k) {
                sz += bz[k] * Wlz[k*Cc + tid];
                sh += bh[k] * Wlh[k*Cc + tid];
            }
            g_cz[tid] = sz + blz[tid];
            g_ch[tid] = sh + blh[tid];
        }
        if (tid == 0) {
            float m = -1e30f;
            for (int t = 0; t < Tt; ++t) m = fmaxf(m, att[t]);
            float ex[Tt], s = 0.f;
            for (int t = 0; t < Tt; ++t) { ex[t] = expf(att[t] - m); s += ex[t]; }
            float inv = 1.f / s;
            for (int t = 0; t < Tt; ++t) g_probs[t] = ex[t] * inv;
        }
    }
}

// ---------------- dis + per-tile scan + last-block tile-total scan ---------
__global__ void k_scan() {
    const float* deg = (const float*)g_zero;
    const int*   cnt = (const int*)(g_zero + Nn);
    __shared__ int sh[TILE];
    int t = threadIdx.x;
    int i = blockIdx.x * TILE + t;
    int v = (i < Nn) ? cnt[i] : 0;
    if (i < Nn) g_dis[i] = rsqrtf(deg[i] + 1.f);
    sh[t] = v;
    __syncthreads();
    #pragma unroll
    for (int off = 1; off < TILE; off <<= 1) {
        int add = (t >= off) ? sh[t - off] : 0;
        __syncthreads();
        sh[t] += add;
        __syncthreads();
    }
    if (i < Nn) { int p = sh[t] - v; g_ptrloc[i] = p; g_cur[i] = p; }
    if (t == TILE - 1) g_tilesum[blockIdx.x] = sh[t];

    // last-arriving block scans the 98 tile sums -> g_tileoff
    __threadfence();
    __shared__ int isLast;
    if (t == 0) {
        unsigned int old = atomicAdd(&g_zero[2*Nn], 1u);
        isLast = (old == NTILES - 1);
    }
    __syncthreads();
    if (isLast) {
        __shared__ int s2[128];
        int w = (t < NTILES) ? g_tilesum[t] : 0;
        if (t < 128) s2[t] = w;
        __syncthreads();
        #pragma unroll
        for (int off = 1; off < 128; off <<= 1) {
            int add = (t < 128 && t >= off) ? s2[t - off] : 0;
            __syncthreads();
            if (t < 128) s2[t] += add;
            __syncthreads();
        }
        if (t < NTILES) g_tileoff[t] = s2[t] - w;   // exclusive
    }
}

// ---------------- scatter edges into CSR slots (packed int2) ---------------
__global__ void k_scatter(const int* __restrict__ ei,
                          const float* __restrict__ ew) {
    int e = blockIdx.x * blockDim.x + threadIdx.x;
    if (e >= Ee) return;
    int r = ei[e];
    int c = ei[Ee + e];
    float nm = g_dis[r] * ew[e] * g_dis[c];
    int pos = atomicAdd(&g_cur[c], 1) + g_tileoff[c >> 9];
    g_edge[pos] = make_int2(r, __float_as_int(nm));
}

// ---------------- fused gather aggregation + GRU-lite epilogue -------------
// one warp per node; 2 edges per iteration, edge data via L1 broadcast loads
__global__ void __launch_bounds__(256) k_aggfinal(
                           const float* __restrict__ x,
                           const float* __restrict__ Wout,
                           const float* __restrict__ bout,
                           float* __restrict__ out) {
    __shared__ float4 s_x[8][12];        // aggregated 48-vector per warp
    __shared__ float  s_h[8][32];        // per-channel h per warp
    __shared__ float  s_w[Cc * HORZ];    // Wout cached per block
    __shared__ float  s_p[Tt];           // probs cached per block

    int tid  = threadIdx.x;
    for (int i = tid; i < Cc * HORZ; i += 256) s_w[i] = Wout[i];
    if (tid < Tt) s_p[tid] = g_probs[tid];
    __syncthreads();

    int warp = (blockIdx.x << 3) + (tid >> 5);
    int wl   = tid >> 5;
    int lane = tid & 31;
    if (warp >= Nn) return;

    int beg = g_ptrloc[warp] + g_tileoff[warp >> 9];
    int end = (warp == Nn - 1) ? Ee
            : (g_ptrloc[warp + 1] + g_tileoff[(warp + 1) >> 9]);
    float d  = g_dis[warp];
    float sn = d * d;

    const float4* __restrict__ X4 = (const float4*)x;   // [n][12] float4
    int  half = (lane >= 12) ? 1 : 0;     // edge slot within pair
    int  q    = lane - 12 * half;         // float4 index 0..11
    bool act  = lane < 24;

    float4 acc = make_float4(0.f, 0.f, 0.f, 0.f);
    if (lane < 12) {                      // self-loop term (half 0 only)
        float4 v = X4[warp * 12 + lane];
        acc.x = sn * v.x; acc.y = sn * v.y; acc.z = sn * v.z; acc.w = sn * v.w;
    }

    // full pairs, no per-edge guard (each half loads its own edge; uniform
    // address within a half -> one broadcast wavefront in L1)
    int k = beg;
    #pragma unroll 2
    for (; k + 1 < end; k += 2) {
        if (act) {
            int2  ed = g_edge[k + half];
            float nn = __int_as_float(ed.y);
            float4 v = X4[ed.x * 12 + q];
            acc.x += nn * v.x; acc.y += nn * v.y;
            acc.z += nn * v.z; acc.w += nn * v.w;
        }
    }
    if (k < end && lane < 12) {           // odd leftover edge (half 0 only)
        int2  ed = g_edge[k];
        float nn = __int_as_float(ed.y);
        float4 v = X4[ed.x * 12 + q];
        acc.x += nn * v.x; acc.y += nn * v.y;
        acc.z += nn * v.z; acc.w += nn * v.w;
    }
    // merge the two edge-slot halves: lane L += lane L+12
    acc.x += __shfl_down_sync(0xffffffffu, acc.x, 12);
    acc.y += __shfl_down_sync(0xffffffffu, acc.y, 12);
    acc.z += __shfl_down_sync(0xffffffffu, acc.z, 12);
    acc.w += __shfl_down_sync(0xffffffffu, acc.w, 12);
    if (lane < 12) s_x[wl][lane] = acc;
    __syncwarp();

    // ----- GRU-lite epilogue: lane = channel; time in float4 groups -----
    float mz0 = g_Mz[lane],        mz1 = g_Mz[Cc + lane];
    float mz2 = g_Mz[2*Cc + lane], mz3 = g_Mz[3*Cc + lane];
    float mh0 = g_Mh[lane],        mh1 = g_Mh[Cc + lane];
    float mh2 = g_Mh[2*Cc + lane], mh3 = g_Mh[3*Cc + lane];
    float cz  = g_cz[lane],        ch  = g_ch[lane];

    float Hacc = 0.f;
    #pragma unroll
    for (int tt = 0; tt < 3; ++tt) {      // t = 4*tt .. 4*tt+3
        float4 a0 = s_x[wl][0*3 + tt];    // feature f, float4 index f*3+tt
        float4 a1 = s_x[wl][1*3 + tt];
        float4 a2 = s_x[wl][2*3 + tt];
        float4 a3 = s_x[wl][3*3 + tt];
        #pragma unroll
        for (int u = 0; u < 4; ++u) {
            float b0 = (&a0.x)[u], b1 = (&a1.x)[u], b2 = (&a2.x)[u], b3 = (&a3.x)[u];
            float zp = cz + b0*mz0 + b1*mz1 + b2*mz2 + b3*mz3;
            float hp = ch + b0*mh0 + b1*mh1 + b2*mh2 + b3*mh3;
            // (1-Z) = 0.5 - 0.5*tanh(zp/2)
            float tz  = tanh_fast(0.5f * zp);
            float th  = tanh_fast(hp);
            float omz = __fmaf_rn(-0.5f, tz, 0.5f);
            Hacc = __fmaf_rn(s_p[4*tt + u] * omz, th, Hacc);   // Hn = (1-Z)*Ht
        }
    }
    float h = fmaxf(Hacc, 0.f);
    s_h[wl][lane] = h;
    __syncwarp();

    // ----- output GEMV: split channels over two half-warps -----
    int  half2 = (lane >= 16) ? 1 : 0;
    int  j     = lane - 16 * half2;      // output index 0..11 (12..15 idle)
    float o = 0.f;
    if (j < HORZ) {
        #pragma unroll
        for (int c = 0; c < Cc; c += 2) {
            int cc = c + half2;
            o += s_h[wl][cc] * s_w[cc * HORZ + j];
        }
    }
    o += __shfl_down_sync(0xffffffffu, o, 16);
    if (lane < HORZ)
        out[warp * HORZ + lane] = o + bout[lane];
}

// ---------------- launch ----------------------------------------------------
extern "C" void kernel_launch(void* const* d_in, const int* in_sizes, int n_in,
                              void* d_out, int out_size) {
    const float* x    = (const float*)d_in[0];
    const int*   ei   = (const int*)d_in[1];     // int32 (JAX x64 disabled)
    const float* ew   = (const float*)d_in[2];
    const float* att  = (const float*)d_in[3];
    const float* Wz   = (const float*)d_in[4];
    const float* bz   = (const float*)d_in[5];
    const float* Wlz  = (const float*)d_in[6];
    const float* blz  = (const float*)d_in[7];
    // d_in[8..11] = Wr, br, Wlr, blr -> dead (H0 == 0 forever)
    const float* Wh   = (const float*)d_in[12];
    const float* bh   = (const float*)d_in[13];
    const float* Wlh  = (const float*)d_in[14];
    const float* blh  = (const float*)d_in[15];
    const float* Wout = (const float*)d_in[16];
    const float* bout = (const float*)d_in[17];
    float*       out  = (float*)d_out;

    void* zp = nullptr;
    cudaGetSymbolAddress(&zp, g_zero);
    cudaMemsetAsync(zp, 0, (2*Nn + 1) * sizeof(unsigned int));

    k_hist<<<(Ee + 255) / 256, 256>>>(ei, ew, att, Wz, bz, Wlz, blz, Wh, bh, Wlh, blh);
    k_scan<<<NTILES, TILE>>>();
    k_scatter<<<(Ee + 255) / 256, 256>>>(ei, ew);
    k_aggfinal<<<(Nn * 32 + 255) / 256, 256>>>(x, Wout, bout, out);
}

// round 11
// speedup vs baseline: 1.0865x; 1.0865x over previous
#include <cuda_runtime.h>

#define Nn    50000
#define Ee    800000
#define Ff    4
#define Tt    12
#define Cc    32
#define HORZ  12
#define FT    (Ff*Tt)     // 48
#define TILE  512
#define NTILES ((Nn + TILE - 1) / TILE)   // 98

// ---------------- scratch (device globals; no allocation allowed) ----------
// zeroed each run by one cudaMemsetAsync:
//   [0, Nn) ull : packed {count:24 | fixed-point weighted degree:40}
//   last uint   : done-counter for last-block scan
__device__ unsigned long long g_packed[Nn];
__device__ unsigned int g_done[1];
__device__ float  g_dis[Nn];
__device__ int    g_ptrloc[Nn];       // tile-local exclusive scan of counts
__device__ int    g_cur[Nn];          // scatter cursors (tile-local)
__device__ int    g_tilesum[NTILES];
__device__ int    g_tileoff[NTILES];  // exclusive scan of tile sums
__device__ int2   g_edge[Ee];         // packed CSR payload {row, norm bits}
__device__ float  g_Mz[Ff*Cc];        // Wz @ Wlz[:C]
__device__ float  g_Mh[Ff*Cc];        // Wh @ Wlh[:C]
__device__ float  g_cz[Cc];           // bz @ Wlz[:C] + blz
__device__ float  g_ch[Cc];
__device__ float  g_probs[Tt];

static __device__ __forceinline__ float tanh_fast(float v) {
    float r;
    asm("tanh.approx.f32 %0, %1;" : "=f"(r) : "f"(v));
    return r;
}

// ---------------- histogram + (block 0) folded-weight setup ---------------
// ONE 64-bit atomic per edge: high 24 bits count, low 40 bits fixed-point deg
__global__ void k_hist(const int* __restrict__ ei, const float* __restrict__ ew,
                       const float* __restrict__ att,
                       const float* __restrict__ Wz, const float* __restrict__ bz,
                       const float* __restrict__ Wlz, const float* __restrict__ blz,
                       const float* __restrict__ Wh, const float* __restrict__ bh,
                       const float* __restrict__ Wlh, const float* __restrict__ blh) {
    int e = blockIdx.x * blockDim.x + threadIdx.x;
    if (e < Ee) {
        int col = ei[Ee + e];
        unsigned long long v = (1ULL << 40)
            + (unsigned long long)(ew[e] * 16777216.0f);   // 2^24 scale
        atomicAdd(&g_packed[col], v);
    }
    // block 0 additionally folds the weights (H0 == 0 forever -> R gate dead,
    // concat collapses: M = W @ Wl[:C], c = b @ Wl[:C] + bl)
    if (blockIdx.x == 0) {
        int tid = threadIdx.x;
        if (tid < Ff*Cc) {
            int f = tid / Cc, c = tid % Cc;
            float sz = 0.f, sh = 0.f;
            #pragma unroll
            for (int k = 0; k < Cc; ++k) {
                sz += Wz[f*Cc + k] * Wlz[k*Cc + c];
                sh += Wh[f*Cc + k] * Wlh[k*Cc + c];
            }
            g_Mz[tid] = sz;
            g_Mh[tid] = sh;
        }
        if (tid < Cc) {
            float sz = 0.f, sh = 0.f;
            #pragma unroll
            for (int k = 0; k < Cc; ++k) {
                sz += bz[k] * Wlz[k*Cc + tid];
                sh += bh[k] * Wlh[k*Cc + tid];
            }
            g_cz[tid] = sz + blz[tid];
            g_ch[tid] = sh + blh[tid];
        }
        if (tid == 0) {
            float m = -1e30f;
            for (int t = 0; t < Tt; ++t) m = fmaxf(m, att[t]);
            float ex[Tt], s = 0.f;
            for (int t = 0; t < Tt; ++t) { ex[t] = expf(att[t] - m); s += ex[t]; }
            float inv = 1.f / s;
            for (int t = 0; t < Tt; ++t) g_probs[t] = ex[t] * inv;
        }
    }
}

// ---------------- dis + per-tile scan + last-block tile-total scan ---------
__global__ void k_scan() {
    __shared__ int sh[TILE];
    int t = threadIdx.x;
    int i = blockIdx.x * TILE + t;
    int v = 0;
    if (i < Nn) {
        unsigned long long p = g_packed[i];
        v = (int)(p >> 40);
        float deg = (float)(p & ((1ULL << 40) - 1)) * (1.0f / 16777216.0f);
        g_dis[i] = rsqrtf(deg + 1.f);
    }
    sh[t] = v;
    __syncthreads();
    #pragma unroll
    for (int off = 1; off < TILE; off <<= 1) {
        int add = (t >= off) ? sh[t - off] : 0;
        __syncthreads();
        sh[t] += add;
        __syncthreads();
    }
    if (i < Nn) { int p = sh[t] - v; g_ptrloc[i] = p; g_cur[i] = p; }
    if (t == TILE - 1) g_tilesum[blockIdx.x] = sh[t];

    // last-arriving block scans the 98 tile sums -> g_tileoff
    __threadfence();
    __shared__ int isLast;
    if (t == 0) {
        unsigned int old = atomicAdd(&g_done[0], 1u);
        isLast = (old == NTILES - 1);
    }
    __syncthreads();
    if (isLast) {
        __shared__ int s2[128];
        int w = (t < NTILES) ? g_tilesum[t] : 0;
        if (t < 128) s2[t] = w;
        __syncthreads();
        #pragma unroll
        for (int off = 1; off < 128; off <<= 1) {
            int add = (t < 128 && t >= off) ? s2[t - off] : 0;
            __syncthreads();
            if (t < 128) s2[t] += add;
            __syncthreads();
        }
        if (t < NTILES) g_tileoff[t] = s2[t] - w;   // exclusive
    }
}

// ---------------- scatter edges into CSR slots (packed int2) ---------------
__global__ void k_scatter(const int* __restrict__ ei,
                          const float* __restrict__ ew) {
    int e = blockIdx.x * blockDim.x + threadIdx.x;
    if (e >= Ee) return;
    int r = ei[e];
    int c = ei[Ee + e];
    float nm = g_dis[r] * ew[e] * g_dis[c];
    int pos = atomicAdd(&g_cur[c], 1) + g_tileoff[c >> 9];
    g_edge[pos] = make_int2(r, __float_as_int(nm));
}

// ---------------- fused gather aggregation + GRU-lite epilogue -------------
// one warp per node; 32 edges block-loaded into registers, SHFL broadcast,
// 2 edges per pair-iteration (12 float4 lanes each), guard-free inner loop
__global__ void __launch_bounds__(256) k_aggfinal(
                           const float* __restrict__ x,
                           const float* __restrict__ Wout,
                           const float* __restrict__ bout,
                           float* __restrict__ out) {
    __shared__ float4 s_x[8][12];        // aggregated 48-vector per warp
    __shared__ float  s_h[8][32];        // per-channel h per warp
    __shared__ float  s_w[Cc * HORZ];    // Wout cached per block
    __shared__ float  s_p[Tt];           // probs cached per block

    int tid  = threadIdx.x;
    for (int i = tid; i < Cc * HORZ; i += 256) s_w[i] = Wout[i];
    if (tid < Tt) s_p[tid] = g_probs[tid];
    __syncthreads();

    int warp = (blockIdx.x << 3) + (tid >> 5);
    int wl   = tid >> 5;
    int lane = tid & 31;
    if (warp >= Nn) return;

    int beg = g_ptrloc[warp] + g_tileoff[warp >> 9];
    int end = (warp == Nn - 1) ? Ee
            : (g_ptrloc[warp + 1] + g_tileoff[(warp + 1) >> 9]);
    float d  = g_dis[warp];
    float sn = d * d;

    const float4* __restrict__ X4 = (const float4*)x;   // [n][12] float4
    int  half = (lane >= 12) ? 1 : 0;     // edge slot within pair
    int  q    = lane - 12 * half;         // float4 index 0..11
    bool act  = lane < 24;

    float4 acc = make_float4(0.f, 0.f, 0.f, 0.f);
    if (lane < 12) {                      // self-loop term (half 0 only)
        float4 v = X4[warp * 12 + lane];
        acc.x = sn * v.x; acc.y = sn * v.y; acc.z = sn * v.z; acc.w = sn * v.w;
    }

    for (int base = beg; base < end; base += 32) {
        int k = base + lane;
        int2 ed = make_int2(0, 0);
        if (k < end) ed = g_edge[k];      // one coalesced LDG.64 per 32 edges
        int cnt = min(32, end - base);
        int i = 0;
        #pragma unroll 2
        for (; i + 1 < cnt; i += 2) {     // full pairs: NO per-edge guard
            int src = i + half;
            int   rr = __shfl_sync(0xffffffffu, ed.x, src);
            float nn = __int_as_float(__shfl_sync(0xffffffffu, ed.y, src));
            if (act) {
                float4 v = X4[rr * 12 + q];
                acc.x += nn * v.x; acc.y += nn * v.y;
                acc.z += nn * v.z; acc.w += nn * v.w;
            }
        }
        if (i < cnt) {                    // odd leftover edge (half 0 only)
            int   rr = __shfl_sync(0xffffffffu, ed.x, i);
            float nn = __int_as_float(__shfl_sync(0xffffffffu, ed.y, i));
            if (lane < 12) {
                float4 v = X4[rr * 12 + q];
                acc.x += nn * v.x; acc.y += nn * v.y;
                acc.z += nn * v.z; acc.w += nn * v.w;
            }
        }
    }
    // merge the two edge-slot halves: lane L += lane L+12
    acc.x += __shfl_down_sync(0xffffffffu, acc.x, 12);
    acc.y += __shfl_down_sync(0xffffffffu, acc.y, 12);
    acc.z += __shfl_down_sync(0xffffffffu, acc.z, 12);
    acc.w += __shfl_down_sync(0xffffffffu, acc.w, 12);
    if (lane < 12) s_x[wl][lane] = acc;
    __syncwarp();

    // ----- GRU-lite epilogue: lane = channel; time in float4 groups -----
    float mz0 = g_Mz[lane],        mz1 = g_Mz[Cc + lane];
    float mz2 = g_Mz[2*Cc + lane], mz3 = g_Mz[3*Cc + lane];
    float mh0 = g_Mh[lane],        mh1 = g_Mh[Cc + lane];
    float mh2 = g_Mh[2*Cc + lane], mh3 = g_Mh[3*Cc + lane];
    float cz  = g_cz[lane],        ch  = g_ch[lane];

    float Hacc = 0.f;
    #pragma unroll
    for (int tt = 0; tt < 3; ++tt) {      // t = 4*tt .. 4*tt+3
        float4 a0 = s_x[wl][0*3 + tt];    // feature f, float4 index f*3+tt
        float4 a1 = s_x[wl][1*3 + tt];
        float4 a2 = s_x[wl][2*3 + tt];
        float4 a3 = s_x[wl][3*3 + tt];
        #pragma unroll
        for (int u = 0; u < 4; ++u) {
            float b0 = (&a0.x)[u], b1 = (&a1.x)[u], b2 = (&a2.x)[u], b3 = (&a3.x)[u];
            float zp = cz + b0*mz0 + b1*mz1 + b2*mz2 + b3*mz3;
            float hp = ch + b0*mh0 + b1*mh1 + b2*mh2 + b3*mh3;
            // (1-Z) = 0.5 - 0.5*tanh(zp/2)
            float tz  = tanh_fast(0.5f * zp);
            float th  = tanh_fast(hp);
            float omz = __fmaf_rn(-0.5f, tz, 0.5f);
            Hacc = __fmaf_rn(s_p[4*tt + u] * omz, th, Hacc);   // Hn = (1-Z)*Ht
        }
    }
    float h = fmaxf(Hacc, 0.f);
    s_h[wl][lane] = h;
    __syncwarp();

    // ----- output GEMV: split channels over two half-warps -----
    int  half2 = (lane >= 16) ? 1 : 0;
    int  j     = lane - 16 * half2;      // output index 0..11 (12..15 idle)
    float o = 0.f;
    if (j < HORZ) {
        #pragma unroll
        for (int c = 0; c < Cc; c += 2) {
            int cc = c + half2;
            o += s_h[wl][cc] * s_w[cc * HORZ + j];
        }
    }
    o += __shfl_down_sync(0xffffffffu, o, 16);
    if (lane < HORZ)
        out[warp * HORZ + lane] = o + bout[lane];
}

// ---------------- launch ----------------------------------------------------
extern "C" void kernel_launch(void* const* d_in, const int* in_sizes, int n_in,
                              void* d_out, int out_size) {
    const float* x    = (const float*)d_in[0];
    const int*   ei   = (const int*)d_in[1];     // int32 (JAX x64 disabled)
    const float* ew   = (const float*)d_in[2];
    const float* att  = (const float*)d_in[3];
    const float* Wz   = (const float*)d_in[4];
    const float* bz   = (const float*)d_in[5];
    const float* Wlz  = (const float*)d_in[6];
    const float* blz  = (const float*)d_in[7];
    // d_in[8..11] = Wr, br, Wlr, blr -> dead (H0 == 0 forever)
    const float* Wh   = (const float*)d_in[12];
    const float* bh   = (const float*)d_in[13];
    const float* Wlh  = (const float*)d_in[14];
    const float* blh  = (const float*)d_in[15];
    const float* Wout = (const float*)d_in[16];
    const float* bout = (const float*)d_in[17];
    float*       out  = (float*)d_out;

    void* zp = nullptr;
    cudaGetSymbolAddress(&zp, g_packed);
    cudaMemsetAsync(zp, 0, Nn * sizeof(unsigned long long));
    void* dp = nullptr;
    cudaGetSymbolAddress(&dp, g_done);
    cudaMemsetAsync(dp, 0, sizeof(unsigned int));

    k_hist<<<(Ee + 255) / 256, 256>>>(ei, ew, att, Wz, bz, Wlz, blz, Wh, bh, Wlh, blh);
    k_scan<<<NTILES, TILE>>>();
    k_scatter<<<(Ee + 255) / 256, 256>>>(ei, ew);
    k_aggfinal<<<(Nn * 32 + 255) / 256, 256>>>(x, Wout, bout, out);
}

// round 15
// speedup vs baseline: 1.1490x; 1.0576x over previous
#include <cuda_runtime.h>

#define Nn    50000
#define Ee    800000
#define Ff    4
#define Tt    12
#define Cc    32
#define HORZ  12
#define FT    (Ff*Tt)     // 48
#define TILE  512
#define NTILES ((Nn + TILE - 1) / TILE)   // 98

// ---------------- scratch (device globals; no allocation allowed) ----------
// zeroed each run by ONE cudaMemsetAsync:
//   [0, Nn) ull : packed {count:24 | fixed-point weighted degree:40}
//   [Nn]    ull : done-counter for last-block scan (low 32 bits)
__device__ unsigned long long g_packed[Nn + 1];
__device__ float  g_dis[Nn];
__device__ int    g_ptrloc[Nn];       // tile-local exclusive scan of counts
__device__ int    g_cur[Nn];          // scatter cursors (tile-local)
__device__ int    g_tilesum[NTILES];
__device__ int    g_tileoff[NTILES];  // exclusive scan of tile sums
__device__ int2   g_edge[Ee];         // packed CSR payload {row*12, norm bits}
__device__ float  g_Mz[Ff*Cc];        // Wz @ Wlz[:C]
__device__ float  g_Mh[Ff*Cc];        // Wh @ Wlh[:C]
__device__ float  g_cz[Cc];           // bz @ Wlz[:C] + blz
__device__ float  g_ch[Cc];
__device__ float  g_probs[Tt];

static __device__ __forceinline__ float tanh_fast(float v) {
    float r;
    asm("tanh.approx.f32 %0, %1;" : "=f"(r) : "f"(v));
    return r;
}

// ---------------- histogram + (block 0) folded-weight setup ---------------
// ONE 64-bit atomic per edge: high 24 bits count, low 40 bits fixed-point deg
__global__ void k_hist(const int* __restrict__ ei, const float* __restrict__ ew,
                       const float* __restrict__ att,
                       const float* __restrict__ Wz, const float* __restrict__ bz,
                       const float* __restrict__ Wlz, const float* __restrict__ blz,
                       const float* __restrict__ Wh, const float* __restrict__ bh,
                       const float* __restrict__ Wlh, const float* __restrict__ blh) {
    int e = blockIdx.x * blockDim.x + threadIdx.x;
    if (e < Ee) {
        int col = ei[Ee + e];
        unsigned long long v = (1ULL << 40)
            + (unsigned long long)(ew[e] * 16777216.0f);   // 2^24 scale
        atomicAdd(&g_packed[col], v);
    }
    // block 0 additionally folds the weights (H0 == 0 forever -> R gate dead,
    // concat collapses: M = W @ Wl[:C], c = b @ Wl[:C] + bl)
    if (blockIdx.x == 0) {
        int tid = threadIdx.x;
        if (tid < Ff*Cc) {
            int f = tid / Cc, c = tid % Cc;
            float sz = 0.f, sh = 0.f;
            #pragma unroll
            for (int k = 0; k < Cc; ++k) {
                sz += Wz[f*Cc + k] * Wlz[k*Cc + c];
                sh += Wh[f*Cc + k] * Wlh[k*Cc + c];
            }
            g_Mz[tid] = sz;
            g_Mh[tid] = sh;
        }
        if (tid < Cc) {
            float sz = 0.f, sh = 0.f;
            #pragma unroll
            for (int k = 0; k < Cc; ++k) {
                sz += bz[k] * Wlz[k*Cc + tid];
                sh += bh[k] * Wlh[k*Cc + tid];
            }
            g_cz[tid] = sz + blz[tid];
            g_ch[tid] = sh + blh[tid];
        }
        if (tid == 0) {
            float m = -1e30f;
            for (int t = 0; t < Tt; ++t) m = fmaxf(m, att[t]);
            float ex[Tt], s = 0.f;
            for (int t = 0; t < Tt; ++t) { ex[t] = expf(att[t] - m); s += ex[t]; }
            float inv = 1.f / s;
            for (int t = 0; t < Tt; ++t) g_probs[t] = ex[t] * inv;
        }
    }
}

// ---------------- dis + per-tile scan + last-block tile-total scan ---------
__global__ void k_scan() {
    __shared__ int sh[TILE];
    int t = threadIdx.x;
    int i = blockIdx.x * TILE + t;
    int v = 0;
    if (i < Nn) {
        unsigned long long p = g_packed[i];
        v = (int)(p >> 40);
        float deg = (float)(p & ((1ULL << 40) - 1)) * (1.0f / 16777216.0f);
        g_dis[i] = rsqrtf(deg + 1.f);
    }
    sh[t] = v;
    __syncthreads();
    #pragma unroll
    for (int off = 1; off < TILE; off <<= 1) {
        int add = (t >= off) ? sh[t - off] : 0;
        __syncthreads();
        sh[t] += add;
        __syncthreads();
    }
    if (i < Nn) { int p = sh[t] - v; g_ptrloc[i] = p; g_cur[i] = p; }
    if (t == TILE - 1) g_tilesum[blockIdx.x] = sh[t];

    // last-arriving block scans the 98 tile sums -> g_tileoff
    __threadfence();
    __shared__ int isLast;
    if (t == 0) {
        unsigned int* done = (unsigned int*)&g_packed[Nn];
        unsigned int old = atomicAdd(done, 1u);
        isLast = (old == NTILES - 1);
    }
    __syncthreads();
    if (isLast) {
        __shared__ int s2[128];
        int w = (t < NTILES) ? g_tilesum[t] : 0;
        if (t < 128) s2[t] = w;
        __syncthreads();
        #pragma unroll
        for (int off = 1; off < 128; off <<= 1) {
            int add = (t < 128 && t >= off) ? s2[t - off] : 0;
            __syncthreads();
            if (t < 128) s2[t] += add;
            __syncthreads();
        }
        if (t < NTILES) g_tileoff[t] = s2[t] - w;   // exclusive
    }
}

// ---------------- scatter edges into CSR slots (packed int2) ---------------
// stores PRE-MULTIPLIED row index (r*12 = float4 row offset)
__global__ void k_scatter(const int* __restrict__ ei,
                          const float* __restrict__ ew) {
    int e = blockIdx.x * blockDim.x + threadIdx.x;
    if (e >= Ee) return;
    int r = ei[e];
    int c = ei[Ee + e];
    float nm = g_dis[r] * ew[e] * g_dis[c];
    int pos = atomicAdd(&g_cur[c], 1) + g_tileoff[c >> 9];
    g_edge[pos] = make_int2(r * 12, __float_as_int(nm));
}

// ---------------- fused gather aggregation + GRU-lite epilogue -------------
// one warp per node; 32 edges block-loaded into registers, SHFL broadcast,
// 2 edges per pair-iteration; 128-thread blocks to cut degree-tail imbalance
__global__ void __launch_bounds__(128) k_aggfinal(
                           const float* __restrict__ x,
                           const float* __restrict__ Wout,
                           const float* __restrict__ bout,
                           float* __restrict__ out) {
    __shared__ float4 s_x[4][12];        // aggregated 48-vector per warp
    __shared__ float  s_h[4][32];        // per-channel h per warp
    __shared__ float  s_w[Cc * HORZ];    // Wout cached per block
    __shared__ float  s_p[Tt];           // probs cached per block

    int tid  = threadIdx.x;
    for (int i = tid; i < Cc * HORZ; i += 128) s_w[i] = Wout[i];
    if (tid < Tt) s_p[tid] = g_probs[tid];
    __syncthreads();

    int warp = (blockIdx.x << 2) + (tid >> 5);
    int wl   = tid >> 5;
    int lane = tid & 31;
    if (warp >= Nn) return;

    int beg = g_ptrloc[warp] + g_tileoff[warp >> 9];
    int end = (warp == Nn - 1) ? Ee
            : (g_ptrloc[warp + 1] + g_tileoff[(warp + 1) >> 9]);
    float d  = g_dis[warp];
    float sn = d * d;

    const float4* __restrict__ X4 = (const float4*)x;   // [n][12] float4
    int  half = (lane >= 12) ? 1 : 0;     // edge slot within pair
    int  q    = lane - 12 * half;         // float4 index 0..11
    bool act  = lane < 24;

    float4 acc = make_float4(0.f, 0.f, 0.f, 0.f);
    if (lane < 12) {                      // self-loop term (half 0 only)
        float4 v = X4[warp * 12 + lane];
        acc.x = sn * v.x; acc.y = sn * v.y; acc.z = sn * v.z; acc.w = sn * v.w;
    }

    for (int base = beg; base < end; base += 32) {
        int k = base + lane;
        int2 ed = make_int2(0, 0);
        if (k < end) ed = g_edge[k];      // one coalesced LDG.64 per 32 edges
        int cnt = min(32, end - base);
        int i = 0;
        #pragma unroll 2
        for (; i + 1 < cnt; i += 2) {     // full pairs: NO per-edge guard
            int src = i + half;
            int   ro = __shfl_sync(0xffffffffu, ed.x, src);   // pre-mult r*12
            float nn = __int_as_float(__shfl_sync(0xffffffffu, ed.y, src));
            if (act) {
                float4 v = X4[ro + q];
                acc.x += nn * v.x; acc.y += nn * v.y;
                acc.z += nn * v.z; acc.w += nn * v.w;
            }
        }
        if (i < cnt) {                    // odd leftover edge (half 0 only)
            int   ro = __shfl_sync(0xffffffffu, ed.x, i);
            float nn = __int_as_float(__shfl_sync(0xffffffffu, ed.y, i));
            if (lane < 12) {
                float4 v = X4[ro + q];
                acc.x += nn * v.x; acc.y += nn * v.y;
                acc.z += nn * v.z; acc.w += nn * v.w;
            }
        }
    }
    // merge the two edge-slot halves: lane L += lane L+12
    acc.x += __shfl_down_sync(0xffffffffu, acc.x, 12);
    acc.y += __shfl_down_sync(0xffffffffu, acc.y, 12);
    acc.z += __shfl_down_sync(0xffffffffu, acc.z, 12);
    acc.w += __shfl_down_sync(0xffffffffu, acc.w, 12);
    if (lane < 12) s_x[wl][lane] = acc;
    __syncwarp();

    // ----- GRU-lite epilogue: lane = channel; time in float4 groups -----
    float mz0 = g_Mz[lane],        mz1 = g_Mz[Cc + lane];
    float mz2 = g_Mz[2*Cc + lane], mz3 = g_Mz[3*Cc + lane];
    float mh0 = g_Mh[lane],        mh1 = g_Mh[Cc + lane];
    float mh2 = g_Mh[2*Cc + lane], mh3 = g_Mh[3*Cc + lane];
    float cz  = g_cz[lane],        ch  = g_ch[lane];

    float Hacc = 0.f;
    #pragma unroll
    for (int tt = 0; tt < 3; ++tt) {      // t = 4*tt .. 4*tt+3
        float4 a0 = s_x[wl][0*3 + tt];    // feature f, float4 index f*3+tt
        float4 a1 = s_x[wl][1*3 + tt];
        float4 a2 = s_x[wl][2*3 + tt];
        float4 a3 = s_x[wl][3*3 + tt];
        #pragma unroll
        for (int u = 0; u < 4; ++u) {
            float b0 = (&a0.x)[u], b1 = (&a1.x)[u], b2 = (&a2.x)[u], b3 = (&a3.x)[u];
            float zp = cz + b0*mz0 + b1*mz1 + b2*mz2 + b3*mz3;
            float hp = ch + b0*mh0 + b1*mh1 + b2*mh2 + b3*mh3;
            // (1-Z) = 0.5 - 0.5*tanh(zp/2)
            float tz  = tanh_fast(0.5f * zp);
            float th  = tanh_fast(hp);
            float omz = __fmaf_rn(-0.5f, tz, 0.5f);
            Hacc = __fmaf_rn(s_p[4*tt + u] * omz, th, Hacc);   // Hn = (1-Z)*Ht
        }
    }
    float h = fmaxf(Hacc, 0.f);
    s_h[wl][lane] = h;
    __syncwarp();

    // ----- output GEMV: split channels over two half-warps -----
    int  half2 = (lane >= 16) ? 1 : 0;
    int  j     = lane - 16 * half2;      // output index 0..11 (12..15 idle)
    float o = 0.f;
    if (j < HORZ) {
        #pragma unroll
        for (int c = 0; c < Cc; c += 2) {
            int cc = c + half2;
            o += s_h[wl][cc] * s_w[cc * HORZ + j];
        }
    }
    o += __shfl_down_sync(0xffffffffu, o, 16);
    if (lane < HORZ)
        out[warp * HORZ + lane] = o + bout[lane];
}

// ---------------- launch ----------------------------------------------------
extern "C" void kernel_launch(void* const* d_in, const int* in_sizes, int n_in,
                              void* d_out, int out_size) {
    const float* x    = (const float*)d_in[0];
    const int*   ei   = (const int*)d_in[1];     // int32 (JAX x64 disabled)
    const float* ew   = (const float*)d_in[2];
    const float* att  = (const float*)d_in[3];
    const float* Wz   = (const float*)d_in[4];
    const float* bz   = (const float*)d_in[5];
    const float* Wlz  = (const float*)d_in[6];
    const float* blz  = (const float*)d_in[7];
    // d_in[8..11] = Wr, br, Wlr, blr -> dead (H0 == 0 forever)
    const float* Wh   = (const float*)d_in[12];
    const float* bh   = (const float*)d_in[13];
    const float* Wlh  = (const float*)d_in[14];
    const float* blh  = (const float*)d_in[15];
    const float* Wout = (const float*)d_in[16];
    const float* bout = (const float*)d_in[17];
    float*       out  = (float*)d_out;

    void* zp = nullptr;
    cudaGetSymbolAddress(&zp, g_packed);
    cudaMemsetAsync(zp, 0, (Nn + 1) * sizeof(unsigned long long));

    k_hist<<<(Ee + 255) / 256, 256>>>(ei, ew, att, Wz, bz, Wlz, blz, Wh, bh, Wlh, blh);
    k_scan<<<NTILES, TILE>>>();
    k_scatter<<<(Ee + 255) / 256, 256>>>(ei, ew);
    k_aggfinal<<<(Nn + 3) / 4, 128>>>(x, Wout, bout, out);
}

// round 16
// speedup vs baseline: 1.1883x; 1.0341x over previous
#include <cuda_runtime.h>

#define Nn    50000
#define Ee    800000
#define Ff    4
#define Tt    12
#define Cc    32
#define HORZ  12
#define FT    (Ff*Tt)     // 48
#define TILE  512
#define NTILES ((Nn + TILE - 1) / TILE)   // 98

// ---------------- scratch (device globals; no allocation allowed) ----------
// zeroed each run by ONE cudaMemsetAsync:
//   [0, Nn) ull : packed {count:24 | fixed-point weighted degree:40}
//   [Nn]    ull : done-counter for last-block scan (low 32 bits)
__device__ unsigned long long g_packed[Nn + 1];
__device__ float  g_dis[Nn];
__device__ int    g_ptrloc[Nn];       // tile-local exclusive scan of counts
__device__ int    g_cur[Nn];          // scatter cursors (tile-local)
__device__ int    g_tilesum[NTILES];
__device__ int    g_tileoff[NTILES];  // exclusive scan of tile sums
__device__ int2   g_edge[Ee];         // packed CSR payload {row*12, norm bits}
__device__ float  g_Mz[Ff*Cc];        // 0.5 * Wz @ Wlz[:C]   (pre-halved)
__device__ float  g_Mh[Ff*Cc];        // Wh @ Wlh[:C]
__device__ float  g_cz[Cc];           // 0.5 * (bz @ Wlz[:C] + blz)
__device__ float  g_ch[Cc];
__device__ float  g_probs[Tt];        // 0.5 * softmax(att)   (pre-halved)

static __device__ __forceinline__ float tanh_fast(float v) {
    float r;
    asm("tanh.approx.f32 %0, %1;" : "=f"(r) : "f"(v));
    return r;
}

// ---------------- histogram + (block 0) folded-weight setup ---------------
// ONE 64-bit atomic per edge: high 24 bits count, low 40 bits fixed-point deg
__global__ void k_hist(const int* __restrict__ ei, const float* __restrict__ ew,
                       const float* __restrict__ att,
                       const float* __restrict__ Wz, const float* __restrict__ bz,
                       const float* __restrict__ Wlz, const float* __restrict__ blz,
                       const float* __restrict__ Wh, const float* __restrict__ bh,
                       const float* __restrict__ Wlh, const float* __restrict__ blh) {
    int e = blockIdx.x * blockDim.x + threadIdx.x;
    if (e < Ee) {
        int col = ei[Ee + e];
        unsigned long long v = (1ULL << 40)
            + (unsigned long long)(ew[e] * 16777216.0f);   // 2^24 scale
        atomicAdd(&g_packed[col], v);
    }
    // block 0 additionally folds the weights (H0 == 0 forever -> R gate dead,
    // concat collapses: M = W @ Wl[:C], c = b @ Wl[:C] + bl).
    // Z-branch constants are PRE-HALVED: sigmoid(z) = 0.5 + 0.5*tanh(0.5*z),
    // so we bake the 0.5 into Mz/cz and probs to save per-step FMULs.
    if (blockIdx.x == 0) {
        int tid = threadIdx.x;
        if (tid < Ff*Cc) {
            int f = tid / Cc, c = tid % Cc;
            float sz = 0.f, sh = 0.f;
            #pragma unroll
            for (int k = 0; k < Cc; ++k) {
                sz += Wz[f*Cc + k] * Wlz[k*Cc + c];
                sh += Wh[f*Cc + k] * Wlh[k*Cc + c];
            }
            g_Mz[tid] = 0.5f * sz;
            g_Mh[tid] = sh;
        }
        if (tid < Cc) {
            float sz = 0.f, sh = 0.f;
            #pragma unroll
            for (int k = 0; k < Cc; ++k) {
                sz += bz[k] * Wlz[k*Cc + tid];
                sh += bh[k] * Wlh[k*Cc + tid];
            }
            g_cz[tid] = 0.5f * (sz + blz[tid]);
            g_ch[tid] = sh + blh[tid];
        }
        if (tid == 0) {
            float m = -1e30f;
            for (int t = 0; t < Tt; ++t) m = fmaxf(m, att[t]);
            float ex[Tt], s = 0.f;
            for (int t = 0; t < Tt; ++t) { ex[t] = expf(att[t] - m); s += ex[t]; }
            float inv = 0.5f / s;                 // pre-halved
            for (int t = 0; t < Tt; ++t) g_probs[t] = ex[t] * inv;
        }
    }
}

// ---------------- dis + per-tile scan + last-block tile-total scan ---------
__global__ void k_scan() {
    __shared__ int sh[TILE];
    int t = threadIdx.x;
    int i = blockIdx.x * TILE + t;
    int v = 0;
    if (i < Nn) {
        unsigned long long p = g_packed[i];
        v = (int)(p >> 40);
        float deg = (float)(p & ((1ULL << 40) - 1)) * (1.0f / 16777216.0f);
        g_dis[i] = rsqrtf(deg + 1.f);
    }
    sh[t] = v;
    __syncthreads();
    #pragma unroll
    for (int off = 1; off < TILE; off <<= 1) {
        int add = (t >= off) ? sh[t - off] : 0;
        __syncthreads();
        sh[t] += add;
        __syncthreads();
    }
    if (i < Nn) { int p = sh[t] - v; g_ptrloc[i] = p; g_cur[i] = p; }
    if (t == TILE - 1) g_tilesum[blockIdx.x] = sh[t];

    // last-arriving block scans the 98 tile sums -> g_tileoff
    __threadfence();
    __shared__ int isLast;
    if (t == 0) {
        unsigned int* done = (unsigned int*)&g_packed[Nn];
        unsigned int old = atomicAdd(done, 1u);
        isLast = (old == NTILES - 1);
    }
    __syncthreads();
    if (isLast) {
        __shared__ int s2[128];
        int w = (t < NTILES) ? g_tilesum[t] : 0;
        if (t < 128) s2[t] = w;
        __syncthreads();
        #pragma unroll
        for (int off = 1; off < 128; off <<= 1) {
            int add = (t < 128 && t >= off) ? s2[t - off] : 0;
            __syncthreads();
            if (t < 128) s2[t] += add;
            __syncthreads();
        }
        if (t < NTILES) g_tileoff[t] = s2[t] - w;   // exclusive
    }
}

// ---------------- scatter edges into CSR slots (packed int2) ---------------
// stores PRE-MULTIPLIED row index (r*12 = float4 row offset)
__global__ void k_scatter(const int* __restrict__ ei,
                          const float* __restrict__ ew) {
    int e = blockIdx.x * blockDim.x + threadIdx.x;
    if (e >= Ee) return;
    int r = ei[e];
    int c = ei[Ee + e];
    float nm = g_dis[r] * ew[e] * g_dis[c];
    int pos = atomicAdd(&g_cur[c], 1) + g_tileoff[c >> 9];
    g_edge[pos] = make_int2(r * 12, __float_as_int(nm));
}

// ---------------- fused gather aggregation + GRU-lite epilogue -------------
// one warp per node; 32 edges block-loaded into registers, SHFL broadcast,
// 2 edges per pair-iteration; forced 32-reg / full-occupancy build
__global__ void __launch_bounds__(128, 16) k_aggfinal(
                           const float* __restrict__ x,
                           const float* __restrict__ Wout,
                           const float* __restrict__ bout,
                           float* __restrict__ out) {
    __shared__ float4 s_x[4][12];        // aggregated 48-vector per warp
    __shared__ float  s_h[4][32];        // per-channel h per warp
    __shared__ float  s_w[Cc * HORZ];    // Wout cached per block
    __shared__ float  s_p[Tt];           // 0.5*probs cached per block

    int tid  = threadIdx.x;
    for (int i = tid; i < Cc * HORZ; i += 128) s_w[i] = Wout[i];
    if (tid < Tt) s_p[tid] = g_probs[tid];
    __syncthreads();

    int warp = (blockIdx.x << 2) + (tid >> 5);
    int wl   = tid >> 5;
    int lane = tid & 31;
    if (warp >= Nn) return;

    int beg = g_ptrloc[warp] + g_tileoff[warp >> 9];
    int end = (warp == Nn - 1) ? Ee
            : (g_ptrloc[warp + 1] + g_tileoff[(warp + 1) >> 9]);
    float d  = g_dis[warp];
    float sn = d * d;

    const float4* __restrict__ X4 = (const float4*)x;   // [n][12] float4
    int  half = (lane >= 12) ? 1 : 0;     // edge slot within pair
    int  q    = lane - 12 * half;         // float4 index 0..11
    bool act  = lane < 24;

    float4 acc = make_float4(0.f, 0.f, 0.f, 0.f);
    if (lane < 12) {                      // self-loop term (half 0 only)
        float4 v = X4[warp * 12 + lane];
        acc.x = sn * v.x; acc.y = sn * v.y; acc.z = sn * v.z; acc.w = sn * v.w;
    }

    for (int base = beg; base < end; base += 32) {
        int k = base + lane;
        int2 ed = make_int2(0, 0);
        if (k < end) ed = g_edge[k];      // one coalesced LDG.64 per 32 edges
        int cnt = min(32, end - base);
        int i = 0;
        #pragma unroll 2
        for (; i + 1 < cnt; i += 2) {     // full pairs: NO per-edge guard
            int src = i + half;
            int   ro = __shfl_sync(0xffffffffu, ed.x, src);   // pre-mult r*12
            float nn = __int_as_float(__shfl_sync(0xffffffffu, ed.y, src));
            if (act) {
                float4 v = X4[ro + q];
                acc.x += nn * v.x; acc.y += nn * v.y;
                acc.z += nn * v.z; acc.w += nn * v.w;
            }
        }
        if (i < cnt) {                    // odd leftover edge (half 0 only)
            int   ro = __shfl_sync(0xffffffffu, ed.x, i);
            float nn = __int_as_float(__shfl_sync(0xffffffffu, ed.y, i));
            if (lane < 12) {
                float4 v = X4[ro + q];
                acc.x += nn * v.x; acc.y += nn * v.y;
                acc.z += nn * v.z; acc.w += nn * v.w;
            }
        }
    }
    // merge the two edge-slot halves: lane L += lane L+12
    acc.x += __shfl_down_sync(0xffffffffu, acc.x, 12);
    acc.y += __shfl_down_sync(0xffffffffu, acc.y, 12);
    acc.z += __shfl_down_sync(0xffffffffu, acc.z, 12);
    acc.w += __shfl_down_sync(0xffffffffu, acc.w, 12);
    if (lane < 12) s_x[wl][lane] = acc;
    __syncwarp();

    // ----- GRU-lite epilogue: lane = channel; time in float4 groups -----
    // Mz/cz pre-halved: (1-Z) = 0.5 - 0.5*tanh(zp')  with zp' = 0.5*zp
    // probs pre-halved: p*(1-Z) = fma(-p', tz, p')
    float mz0 = g_Mz[lane],        mz1 = g_Mz[Cc + lane];
    float mz2 = g_Mz[2*Cc + lane], mz3 = g_Mz[3*Cc + lane];
    float mh0 = g_Mh[lane],        mh1 = g_Mh[Cc + lane];
    float mh2 = g_Mh[2*Cc + lane], mh3 = g_Mh[3*Cc + lane];
    float cz  = g_cz[lane],        ch  = g_ch[lane];

    float Hacc = 0.f;
    #pragma unroll
    for (int tt = 0; tt < 3; ++tt) {      // t = 4*tt .. 4*tt+3
        float4 a0 = s_x[wl][0*3 + tt];    // feature f, float4 index f*3+tt
        float4 a1 = s_x[wl][1*3 + tt];
        float4 a2 = s_x[wl][2*3 + tt];
        float4 a3 = s_x[wl][3*3 + tt];
        #pragma unroll
        for (int u = 0; u < 4; ++u) {
            float b0 = (&a0.x)[u], b1 = (&a1.x)[u], b2 = (&a2.x)[u], b3 = (&a3.x)[u];
            float zp = cz + b0*mz0 + b1*mz1 + b2*mz2 + b3*mz3;   // pre-halved
            float hp = ch + b0*mh0 + b1*mh1 + b2*mh2 + b3*mh3;
            float tz  = tanh_fast(zp);
            float th  = tanh_fast(hp);
            float pp  = s_p[4*tt + u];                            // 0.5*p
            float pomz = __fmaf_rn(-pp, tz, pp);                  // p*(1-Z)
            Hacc = __fmaf_rn(pomz, th, Hacc);                     // += p*(1-Z)*Ht
        }
    }
    float h = fmaxf(Hacc, 0.f);
    s_h[wl][lane] = h;
    __syncwarp();

    // ----- output GEMV: split channels over two half-warps -----
    int  half2 = (lane >= 16) ? 1 : 0;
    int  j     = lane - 16 * half2;      // output index 0..11 (12..15 idle)
    float o = 0.f;
    if (j < HORZ) {
        #pragma unroll
        for (int c = 0; c < Cc; c += 2) {
            int cc = c + half2;
            o += s_h[wl][cc] * s_w[cc * HORZ + j];
        }
    }
    o += __shfl_down_sync(0xffffffffu, o, 16);
    if (lane < HORZ)
        out[warp * HORZ + lane] = o + bout[lane];
}

// ---------------- launch ----------------------------------------------------
extern "C" void kernel_launch(void* const* d_in, const int* in_sizes, int n_in,
                              void* d_out, int out_size) {
    const float* x    = (const float*)d_in[0];
    const int*   ei   = (const int*)d_in[1];     // int32 (JAX x64 disabled)
    const float* ew   = (const float*)d_in[2];
    const float* att  = (const float*)d_in[3];
    const float* Wz   = (const float*)d_in[4];
    const float* bz   = (const float*)d_in[5];
    const float* Wlz  = (const float*)d_in[6];
    const float* blz  = (const float*)d_in[7];
    // d_in[8..11] = Wr, br, Wlr, blr -> dead (H0 == 0 forever)
    const float* Wh   = (const float*)d_in[12];
    const float* bh   = (const float*)d_in[13];
    const float* Wlh  = (const float*)d_in[14];
    const float* blh  = (const float*)d_in[15];
    const float* Wout = (const float*)d_in[16];
    const float* bout = (const float*)d_in[17];
    float*       out  = (float*)d_out;

    void* zp = nullptr;
    cudaGetSymbolAddress(&zp, g_packed);
    cudaMemsetAsync(zp, 0, (Nn + 1) * sizeof(unsigned long long));

    k_hist<<<(Ee + 255) / 256, 256>>>(ei, ew, att, Wz, bz, Wlz, blz, Wh, bh, Wlh, blh);
    k_scan<<<NTILES, TILE>>>();
    k_scatter<<<(Ee + 255) / 256, 256>>>(ei, ew);
    k_aggfinal<<<(Nn + 3) / 4, 128>>>(x, Wout, bout, out);
}